// round 2
// baseline (speedup 1.0000x reference)
#include <cuda_runtime.h>
#include <cuda_bf16.h>
#include <cstdint>

// ============================================================================
// Problem constants
// ============================================================================
#define NQ      4096
#define NREF    65536
#define DIMK    512
#define TOPK    16
#define NS      4                      // N-splits of reference set
#define MBLK    128                    // queries per CTA
#define NTILE   ((NREF / NS) / 128)    // 128 ref tiles of 128 per CTA
#define NCH     (NTILE * 4)            // 4 k-chunks (128) per tile -> 512 chunks
#define NLISTS  (NS * 2)               // 2 scanner threads per row per split

// SMEM layout (byte offsets into dynamic smem)
#define SM_A      0                    // 128 x 512 bf16 (swizzled)     131072
#define SM_B      131072               // 2 x (128 x 128 bf16 swizzled)  65536
#define SM_STAGE  196608               // 128 x 64 fp32 (swizzled)       32768
#define SMEM_TOTAL 229376

// ============================================================================
// Scratch (static device arrays; no allocation anywhere)
// ============================================================================
__device__ __align__(16) __nv_bfloat16 g_refs_bf16[(size_t)NREF * DIMK]; // 64 MB
__device__ __align__(16) __nv_bfloat16 g_xn[(size_t)NQ * DIMK];          // 4 MB
__device__ float g_part[(size_t)NQ * NLISTS * TOPK];                     // 4 MB

// ============================================================================
// Helpers (baseline sm_90/sm_103 ISA only — NO tcgen05 / arch-'a' features)
// ============================================================================
__device__ __forceinline__ uint32_t smem_u32(const void* p) {
    return (uint32_t)__cvta_generic_to_shared(p);
}

__device__ __forceinline__ void cp_async_16(uint32_t dst, const void* src) {
    asm volatile("cp.async.cg.shared.global [%0], [%1], 16;"
                 :: "r"(dst), "l"((unsigned long long)__cvta_generic_to_global(src)) : "memory");
}
#define CP_COMMIT() asm volatile("cp.async.commit_group;" ::: "memory")
#define CP_WAIT(N)  asm volatile("cp.async.wait_group %0;" :: "n"(N) : "memory")

__device__ __forceinline__ void ldsm_x4(uint32_t* r, uint32_t addr) {
    asm volatile("ldmatrix.sync.aligned.m8n8.x4.shared.b16 {%0,%1,%2,%3}, [%4];"
                 : "=r"(r[0]), "=r"(r[1]), "=r"(r[2]), "=r"(r[3]) : "r"(addr));
}

__device__ __forceinline__ void mma16816(float* c, const uint32_t* a, const uint32_t* b) {
    asm volatile("mma.sync.aligned.m16n8k16.row.col.f32.bf16.bf16.f32 "
                 "{%0,%1,%2,%3}, {%4,%5,%6,%7}, {%8,%9}, {%0,%1,%2,%3};"
                 : "+f"(c[0]), "+f"(c[1]), "+f"(c[2]), "+f"(c[3])
                 : "r"(a[0]), "r"(a[1]), "r"(a[2]), "r"(a[3]), "r"(b[0]), "r"(b[1]));
}

__device__ __forceinline__ void topk_insert(float v, float* top, float& thr) {
    if (v > thr) {
        int mi = 0; float mv = top[0];
#pragma unroll
        for (int i = 1; i < TOPK; i++)
            if (top[i] < mv) { mv = top[i]; mi = i; }
        top[mi] = v;
        mv = top[0];
#pragma unroll
        for (int i = 1; i < TOPK; i++) mv = fminf(mv, top[i]);
        thr = mv;
    }
}

// ============================================================================
// Kernel 1: L2-normalize x (fp32) -> g_xn (bf16)
// ============================================================================
__global__ void k_norm(const float* __restrict__ x) {
    int row = blockIdx.x;
    int tid = threadIdx.x;   // 128
    float v[4];
    float ss = 0.f;
#pragma unroll
    for (int j = 0; j < 4; j++) {
        v[j] = x[(size_t)row * DIMK + tid + j * 128];
        ss += v[j] * v[j];
    }
#pragma unroll
    for (int o = 16; o; o >>= 1) ss += __shfl_xor_sync(0xFFFFFFFFu, ss, o);
    __shared__ float sred[4];
    if ((tid & 31) == 0) sred[tid >> 5] = ss;
    __syncthreads();
    float tot = sred[0] + sred[1] + sred[2] + sred[3];
    float inv = 1.0f / fmaxf(sqrtf(tot), 1e-12f);
#pragma unroll
    for (int j = 0; j < 4; j++)
        g_xn[(size_t)row * DIMK + tid + j * 128] = __float2bfloat16(v[j] * inv);
}

// ============================================================================
// Kernel 2: refs fp32 -> bf16
// ============================================================================
__global__ void k_cvt(const float* __restrict__ refs) {
    int n = NREF * DIMK / 2;
    const float2* src = (const float2*)refs;
    __nv_bfloat162* dst = (__nv_bfloat162*)g_refs_bf16;
    for (int i = blockIdx.x * blockDim.x + threadIdx.x; i < n; i += gridDim.x * blockDim.x) {
        float2 v = src[i];
        dst[i] = __floats2bfloat162_rn(v.x, v.y);
    }
}

// ============================================================================
// Kernel 3: mma.sync bf16 GEMM + fused streaming top-16
//   grid = 32 M-blocks x 4 N-splits; 256 threads = 8 warps (2 M x 4 N of 64x32)
// ============================================================================
__global__ __launch_bounds__(256, 1) void k_main() {
    extern __shared__ char smem[];
    const uint32_t sb = smem_u32(smem);
    const int tid = threadIdx.x, wid = tid >> 5, lid = tid & 31;
    const int mw = wid >> 2, nw = wid & 3;
    const int mblock = blockIdx.x & 31;
    const int split  = blockIdx.x >> 5;
    const int nbase  = split * (NREF / NS);

    // ---- load resident A tile: 128 rows x 512 bf16, XOR-swizzled -----------
    {
        int row = tid >> 1, seg = tid & 1;
        const uint4* src = (const uint4*)(g_xn + ((size_t)(mblock * MBLK + row)) * DIMK + seg * 256);
        uint32_t swzr = (uint32_t)(row & 7) << 4;
        char* dstrow = smem + SM_A + row * 1024;
#pragma unroll
        for (int j = 0; j < 32; j++) {
            uint32_t off = (uint32_t)(seg * 512 + j * 16);
            *(uint4*)(dstrow + (off ^ swzr)) = src[j];
        }
    }

    // ---- per-lane ldmatrix address components -------------------------------
    const uint32_t swz = (uint32_t)(lid & 7) << 4;
    const int sub = lid >> 3;
    // A: sub0: m+0,k0  sub1: m+8,k0  sub2: m+0,k8  sub3: m+8,k8
    const int aRow = mw * 64 + (lid & 7) + ((sub & 1) << 3);
    const uint32_t a_kof2 = (uint32_t)(sub >> 1) << 4;   // *8 elems *2B
    const uint32_t aBase = sb + SM_A + (uint32_t)aRow * 1024u;
    // B: sub0: n+0,k0  sub1: n+0,k8  sub2: n+8,k0  sub3: n+8,k8
    const int bRow = nw * 32 + (lid & 7) + ((sub >> 1) << 3);
    const uint32_t b_kof2 = (uint32_t)(sub & 1) << 4;
    const uint32_t bRowByte = (uint32_t)bRow * 256u;

    // ---- state --------------------------------------------------------------
    float acc[4][4][4];
#pragma unroll
    for (int a = 0; a < 4; a++)
#pragma unroll
        for (int b = 0; b < 4; b++)
#pragma unroll
            for (int c = 0; c < 4; c++) acc[a][b][c] = 0.f;

    float top[TOPK];
#pragma unroll
    for (int i = 0; i < TOPK; i++) top[i] = -2.0f;
    float thr = -2.0f;
    const int srow = tid & 127, shalf = tid >> 7;   // scanner mapping
    const uint32_t s_swz = (uint32_t)(srow & 7) << 4;

    // ---- B chunk loader (lambda-free) ---------------------------------------
    // chunk g: tile = g>>2, kc = g&3, 128 rows x 128 bf16 -> 32 KB
    {
        // prefetch chunk 0
        int row = tid >> 1, seg = tid & 1;
        const char* src = (const char*)(g_refs_bf16 +
            ((size_t)(nbase + row)) * DIMK + seg * 64);
        uint32_t dst = sb + SM_B + (uint32_t)row * 256u;
        uint32_t swzr = (uint32_t)(row & 7) << 4;
#pragma unroll
        for (int j = 0; j < 8; j++) {
            uint32_t off = (uint32_t)(seg * 128 + j * 16);
            cp_async_16(dst + (off ^ swzr), src + j * 16);
        }
        CP_COMMIT();
    }

#pragma unroll 1
    for (int g = 0; g < NCH; g++) {
        if (g + 1 < NCH) {
            int g2 = g + 1;
            int row = tid >> 1, seg = tid & 1;
            int tile2 = g2 >> 2, kc2 = g2 & 3;
            const char* src = (const char*)(g_refs_bf16 +
                ((size_t)(nbase + tile2 * 128 + row)) * DIMK + kc2 * 128 + seg * 64);
            uint32_t dst = sb + SM_B + (uint32_t)(g2 & 1) * 32768u + (uint32_t)row * 256u;
            uint32_t swzr = (uint32_t)(row & 7) << 4;
#pragma unroll
            for (int j = 0; j < 8; j++) {
                uint32_t off = (uint32_t)(seg * 128 + j * 16);
                cp_async_16(dst + (off ^ swzr), src + j * 16);
            }
            CP_COMMIT();
            CP_WAIT(1);
        } else {
            CP_WAIT(0);
        }
        __syncthreads();

        // ---- compute chunk g: K=128 = 8 mma k-steps -------------------------
        {
            const uint32_t kc = (uint32_t)(g & 3);
            const uint32_t bbase = sb + SM_B + (uint32_t)(g & 1) * 32768u + bRowByte;
#pragma unroll
            for (int ks = 0; ks < 8; ks++) {
                uint32_t afr[4][4];
#pragma unroll
                for (int mt = 0; mt < 4; mt++)
                    ldsm_x4(afr[mt], aBase + (uint32_t)mt * 16384u +
                            ((kc * 256u + (uint32_t)ks * 32u + a_kof2) ^ swz));
                uint32_t bfr[2][4];
#pragma unroll
                for (int j = 0; j < 2; j++)
                    ldsm_x4(bfr[j], bbase + (uint32_t)j * 4096u +
                            (((uint32_t)ks * 32u + b_kof2) ^ swz));
#pragma unroll
                for (int mt = 0; mt < 4; mt++)
#pragma unroll
                    for (int nt = 0; nt < 4; nt++)
                        mma16816(acc[mt][nt], afr[mt], &bfr[nt >> 1][(nt & 1) * 2]);
            }
        }

        // ---- epilogue every 4 chunks (one 128x128 dot tile done) ------------
        if ((g & 3) == 3) {
#pragma unroll 1
            for (int p = 0; p < 2; p++) {
                if ((nw >> 1) == p) {
                    int colbase = (nw & 1) * 32;
#pragma unroll
                    for (int mt = 0; mt < 4; mt++) {
#pragma unroll
                        for (int nt = 0; nt < 4; nt++) {
                            int r0 = mw * 64 + mt * 16 + (lid >> 2);
                            int col = colbase + nt * 8 + 2 * (lid & 3);
                            uint32_t cb = (uint32_t)(col * 4);
                            char* base0 = smem + SM_STAGE + r0 * 256;
                            char* base1 = base0 + 8 * 256;
                            *(float2*)(base0 + (cb ^ ((uint32_t)(r0 & 7) << 4))) =
                                make_float2(acc[mt][nt][0], acc[mt][nt][1]);
                            *(float2*)(base1 + (cb ^ ((uint32_t)((r0 + 8) & 7) << 4))) =
                                make_float2(acc[mt][nt][2], acc[mt][nt][3]);
                        }
                    }
                }
                __syncthreads();
                // scan: thread (srow, shalf) reads 32 floats of its row
                {
                    const char* base = smem + SM_STAGE + srow * 256;
#pragma unroll
                    for (int jj = 0; jj < 8; jj++) {
                        uint32_t off = ((uint32_t)(shalf * 128 + jj * 16)) ^ s_swz;
                        float4 v = *(const float4*)(base + off);
                        topk_insert(v.x, top, thr);
                        topk_insert(v.y, top, thr);
                        topk_insert(v.z, top, thr);
                        topk_insert(v.w, top, thr);
                    }
                }
                __syncthreads();
            }
            // reset accumulators for next tile
#pragma unroll
            for (int a = 0; a < 4; a++)
#pragma unroll
                for (int b = 0; b < 4; b++)
#pragma unroll
                    for (int c = 0; c < 4; c++) acc[a][b][c] = 0.f;
        } else {
            __syncthreads();
        }
    }

    // ---- write partial top lists -------------------------------------------
    {
        int q = mblock * MBLK + srow;
        float* dst = g_part + ((size_t)q * NLISTS + split * 2 + shalf) * TOPK;
#pragma unroll
        for (int i = 0; i < TOPK; i++) dst[i] = top[i];
    }
}

// ============================================================================
// Kernel 4: merge NLISTS partial top-16s -> final sorted weights
// ============================================================================
__global__ void k_merge(float* __restrict__ out) {
    int q = blockIdx.x * blockDim.x + threadIdx.x;
    if (q >= NQ) return;
    float top[TOPK];
#pragma unroll
    for (int i = 0; i < TOPK; i++) top[i] = -2.0f;
    float thr = -2.0f;
    const float* src = g_part + (size_t)q * (NLISTS * TOPK);
#pragma unroll 1
    for (int i = 0; i < NLISTS * TOPK; i++) topk_insert(src[i], top, thr);
    // sort dots descending (= ascending distance, matching top_k order)
#pragma unroll 1
    for (int a = 0; a < TOPK - 1; a++) {
        int bi = a; float bv = top[a];
#pragma unroll 1
        for (int b = a + 1; b < TOPK; b++)
            if (top[b] > bv) { bv = top[b]; bi = b; }
        top[bi] = top[a]; top[a] = bv;
    }
    float w[TOPK];
    float s = 0.f;
#pragma unroll
    for (int j = 0; j < TOPK; j++) {
        float d2 = fmaxf(2.0f - 2.0f * top[j], 1e-12f);
        float d = sqrtf(d2);
        float wv = expf(-d);
        w[j] = wv; s += wv;
    }
    float inv = 1.0f / fmaxf(s, 1e-12f);
#pragma unroll
    for (int j = 0; j < TOPK; j++) out[(size_t)q * TOPK + j] = w[j] * inv;
}

// ============================================================================
// Launch
// ============================================================================
extern "C" void kernel_launch(void* const* d_in, const int* in_sizes, int n_in,
                              void* d_out, int out_size) {
    const float* x    = (const float*)d_in[0];
    const float* refs = (const float*)d_in[1];
    float* out = (float*)d_out;

    k_norm<<<NQ, 128>>>(x);
    k_cvt<<<2048, 256>>>(refs);
    cudaFuncSetAttribute(k_main, cudaFuncAttributeMaxDynamicSharedMemorySize, SMEM_TOTAL);
    k_main<<<(NQ / MBLK) * NS, 256, SMEM_TOTAL>>>();
    k_merge<<<NQ / 128, 128>>>(out);
}